// round 6
// baseline (speedup 1.0000x reference)
#include <cuda_runtime.h>

// Shapes fixed by the problem: x,f = (B=2, 3, T=5, H=720, W=1280) fp32.
// Output = concat(ow, xw), each (B,3,T,H,W) fp32.
constexpr unsigned B  = 2;
constexpr unsigned C  = 3;
constexpr unsigned T  = 5;
constexpr unsigned H  = 720;
constexpr unsigned W  = 1280;
constexpr unsigned PLANE = H * W;            // 921,600
constexpr unsigned CH    = T * PLANE;        // 4,608,000
constexpr unsigned HALF  = B * C * CH;       // 27,648,000

// Tiling: each CTA covers 64(w) x 8(h) pixels; halo 4 (left/top) + 5 (right/bottom)
constexpr int TW   = 64;
constexpr int TH   = 8;
constexpr int HLO  = 4;                      // covers floor(p - 4.0)
constexpr int HHI  = 5;                      // covers floor(p + 4.99)+1
constexpr int SW   = TW + HLO + HHI;         // 73 cols
constexpr int SH   = TH + HLO + HHI;         // 17 rows
constexpr int PITCH = 75;                    // odd-ish pitch -> spread banks
constexpr int SMCH  = SH * PITCH;            // words per channel tile
constexpr unsigned TILES_W  = W / TW;        // 20
constexpr unsigned TILES_H  = H / TH;        // 90
constexpr unsigned TILES_BT = TILES_W * TILES_H;  // 1800
constexpr unsigned NBLK     = TILES_BT * B * T;   // 18000

__global__ __launch_bounds__(256, 4)
void ImageBWarp_65343632441725_kernel(const float* __restrict__ x,
                                      const float* __restrict__ f,
                                      float* __restrict__ out)
{
    __shared__ float sx[3 * SMCH];           // 3 * 1275 * 4B = 15.3 KB

    unsigned blk  = blockIdx.x;
    unsigned bt   = blk / TILES_BT;
    unsigned tile = blk - bt * TILES_BT;
    unsigned ty   = tile / TILES_W;
    unsigned tx   = tile - ty * TILES_W;

    int org_h = (int)(ty * TH) - HLO;
    int org_w = (int)(tx * TW) - HLO;

    unsigned b    = bt / T;
    unsigned t    = bt - b * T;
    unsigned base = (b * (C * T) + t) * PLANE;
    const float* xb = x + base;

    // ---- cooperative fill of the 3-channel halo tile (coalesced rows) ----
    for (int i = threadIdx.x; i < 3 * SH * SW; i += 256) {
        int c   = i / (SH * SW);
        int rem = i - c * (SH * SW);
        int r   = rem / SW;
        int col = rem - r * SW;
        int gr  = min(max(org_h + r,   0), (int)H - 1);
        int gc  = min(max(org_w + col, 0), (int)W - 1);
        sx[c * SMCH + r * PITCH + col] = __ldg(xb + (unsigned)c * CH + (unsigned)gr * W + (unsigned)gc);
    }
    __syncthreads();

    // ---- per-thread: 2 horizontally adjacent pixels ----
    int warp = threadIdx.x >> 5;
    int lane = threadIdx.x & 31;
    unsigned h  = ty * TH + (unsigned)warp;
    unsigned w0 = tx * TW + (unsigned)(lane * 2);
    unsigned hw = h * W + w0;

    const float2 fx2 = *(const float2*)(f + base + hw);
    const float2 fy2 = *(const float2*)(f + base + CH + hw);
    const float2 wl2 = *(const float2*)(f + base + 2u * CH + hw);

    float fx[2] = {fx2.x, fx2.y};
    float fy[2] = {fy2.x, fy2.y};
    float wl[2] = {wl2.x, wl2.y};

    float m00[2], m10[2], m01[2], m11[2];
    int   cx0[2], cx1[2], cy0[2], cy1[2];
    bool  fast[2];
    float wgt[2], owv[2];

#pragma unroll
    for (int j = 0; j < 2; j++) {
        float gx = (float)(w0 + (unsigned)j) + fx[j];
        float gy = (float)h + fy[j];

        float x0f = floorf(gx);
        float y0f = floorf(gy);
        float wx1 = gx - x0f;
        float wy1 = gy - y0f;
        float wx0 = 1.0f - wx1;
        float wy0 = 1.0f - wy1;

        int ix0 = (int)x0f;
        int iy0 = (int)y0f;
        int ix1 = ix0 + 1;
        int iy1 = iy0 + 1;

        bool vx0 = (unsigned)ix0 < W;
        bool vx1 = (unsigned)ix1 < W;
        bool vy0 = (unsigned)iy0 < H;
        bool vy1 = (unsigned)iy1 < H;

        m00[j] = (vx0 && vy0) ? wx0 * wy0 : 0.0f;
        m10[j] = (vx1 && vy0) ? wx1 * wy0 : 0.0f;
        m01[j] = (vx0 && vy1) ? wx0 * wy1 : 0.0f;
        m11[j] = (vx1 && vy1) ? wx1 * wy1 : 0.0f;

        cx0[j] = min(max(ix0, 0), (int)W - 1);
        cx1[j] = min(max(ix1, 0), (int)W - 1);
        cy0[j] = min(max(iy0, 0), (int)H - 1);
        cy1[j] = min(max(iy1, 0), (int)H - 1);

        // fast iff every (clamped) tap coordinate lies in the smem window
        fast[j] = ((unsigned)(cy0[j] - org_h) < (unsigned)SH) &
                  ((unsigned)(cy1[j] - org_h) < (unsigned)SH) &
                  ((unsigned)(cx0[j] - org_w) < (unsigned)SW) &
                  ((unsigned)(cx1[j] - org_w) < (unsigned)SW);

        wgt[j] = __fdividef(1.0f, 1.0f + __expf(-wl[j]));
        owv[j] = wgt[j] * (m00[j] + m10[j] + m01[j] + m11[j]);
    }

    // precompute smem word indices (valid only when fast[j])
    int s00[2], s10[2], s01[2], s11[2];
#pragma unroll
    for (int j = 0; j < 2; j++) {
        int r0 = cy0[j] - org_h, r1 = cy1[j] - org_h;
        int c0 = cx0[j] - org_w, c1 = cx1[j] - org_w;
        s00[j] = r0 * PITCH + c0;
        s10[j] = r0 * PITCH + c1;
        s01[j] = r1 * PITCH + c0;
        s11[j] = r1 * PITCH + c1;
    }

    float* out_ow = out + base + hw;
    float* out_xw = out_ow + HALF;

#pragma unroll
    for (int c = 0; c < 3; c++) {
        const float* sc = sx + c * SMCH;
        const float* xc = xb + (unsigned)c * CH;
        float s[2];
#pragma unroll
        for (int j = 0; j < 2; j++) {
            float v00, v10, v01, v11;
            if (fast[j]) {
                v00 = sc[s00[j]];
                v10 = sc[s10[j]];
                v01 = sc[s01[j]];
                v11 = sc[s11[j]];
            } else {   // rare: |flow| > ~4 px
                v00 = __ldg(xc + (unsigned)cy0[j] * W + (unsigned)cx0[j]);
                v10 = __ldg(xc + (unsigned)cy0[j] * W + (unsigned)cx1[j]);
                v01 = __ldg(xc + (unsigned)cy1[j] * W + (unsigned)cx0[j]);
                v11 = __ldg(xc + (unsigned)cy1[j] * W + (unsigned)cx1[j]);
            }
            s[j] = (m00[j] * v00 + m10[j] * v10 + m01[j] * v01 + m11[j] * v11) * wgt[j];
        }
        *(float2*)(out_ow + (unsigned)c * CH) = make_float2(owv[0], owv[1]);
        *(float2*)(out_xw + (unsigned)c * CH) = make_float2(s[0], s[1]);
    }
}

extern "C" void kernel_launch(void* const* d_in, const int* in_sizes, int n_in,
                              void* d_out, int out_size)
{
    const float* x = (const float*)d_in[0];
    const float* f = (const float*)d_in[1];
    float* out = (float*)d_out;

    ImageBWarp_65343632441725_kernel<<<NBLK, 256>>>(x, f, out);
}

// round 7
// speedup vs baseline: 2.9885x; 2.9885x over previous
#include <cuda_runtime.h>

// Shapes fixed by the problem: x,f = (B=2, 3, T=5, H=720, W=1280) fp32.
// Output = concat(ow, xw), each (B,3,T,H,W) fp32.
constexpr unsigned B  = 2;
constexpr unsigned C  = 3;
constexpr unsigned T  = 5;
constexpr unsigned H  = 720;
constexpr unsigned W  = 1280;
constexpr unsigned PLANE = H * W;            // 921,600
constexpr unsigned CH    = T * PLANE;        // 4,608,000
constexpr unsigned HALF  = B * C * CH;       // 27,648,000

// grid: x -> 10 segments of 128 px, y -> 180 groups of 4 rows, z -> (b,t)
// block: (64, 4) = 256 threads, each thread 2 horizontally adjacent px.

__global__ __launch_bounds__(256)
void ImageBWarp_65343632441725_kernel(const float* __restrict__ x,
                                      const float* __restrict__ f,
                                      float* __restrict__ out)
{
    // zero-division index decode
    unsigned w0 = (blockIdx.x * 64u + threadIdx.x) * 2u;
    unsigned h  = blockIdx.y * 4u + threadIdx.y;
    unsigned bt = blockIdx.z;                 // b*T + t
    unsigned b  = bt / T;                     // div by constant 5 (mul-shift)
    unsigned base = (bt + b * ((C - 1) * T)) * PLANE;   // (b*C*T + t)*PLANE
    unsigned hw   = h * W + w0;               // 8B-aligned

    const float2 fx2 = *(const float2*)(f + base + hw);
    const float2 fy2 = *(const float2*)(f + base + CH + hw);
    const float2 wl2 = *(const float2*)(f + base + 2u * CH + hw);

    float fx[2] = {fx2.x, fx2.y};
    float fy[2] = {fy2.x, fy2.y};
    float wl[2] = {wl2.x, wl2.y};

    float m00[2], m10[2], m01[2], m11[2];
    unsigned o00[2], o10[2], o01[2], o11[2];
    float wgt[2], owv[2];

#pragma unroll
    for (int j = 0; j < 2; j++) {
        float gx = (float)(w0 + (unsigned)j) + fx[j];
        float gy = (float)h + fy[j];

        float x0f = floorf(gx);
        float y0f = floorf(gy);
        float wx1 = gx - x0f;
        float wy1 = gy - y0f;
        float wx0 = 1.0f - wx1;
        float wy0 = 1.0f - wy1;

        int ix0 = (int)x0f;
        int iy0 = (int)y0f;
        int ix1 = ix0 + 1;
        int iy1 = iy0 + 1;

        bool vx0 = (unsigned)ix0 < W;
        bool vx1 = (unsigned)ix1 < W;
        bool vy0 = (unsigned)iy0 < H;
        bool vy1 = (unsigned)iy1 < H;

        m00[j] = (vx0 && vy0) ? wx0 * wy0 : 0.0f;
        m10[j] = (vx1 && vy0) ? wx1 * wy0 : 0.0f;
        m01[j] = (vx0 && vy1) ? wx0 * wy1 : 0.0f;
        m11[j] = (vx1 && vy1) ? wx1 * wy1 : 0.0f;

        unsigned cx0 = (unsigned)min(max(ix0, 0), (int)W - 1);
        unsigned cx1 = (unsigned)min(max(ix1, 0), (int)W - 1);
        unsigned cy0 = (unsigned)min(max(iy0, 0), (int)H - 1);
        unsigned cy1 = (unsigned)min(max(iy1, 0), (int)H - 1);

        o00[j] = cy0 * W + cx0;
        o10[j] = cy0 * W + cx1;
        o01[j] = cy1 * W + cx0;
        o11[j] = cy1 * W + cx1;

        // sigmoid via HW tanh: sigmoid(x) = 0.5*tanh(x/2) + 0.5
        wgt[j] = 0.5f * __tanhf(0.5f * wl[j]) + 0.5f;
        owv[j] = wgt[j] * (m00[j] + m10[j] + m01[j] + m11[j]);
    }

    // store the 3 identical ow planes first: overlaps with gather latency,
    // frees owv registers before the gather loop
    float* out_ow = out + base + hw;
    {
        float2 ow2 = make_float2(owv[0], owv[1]);
        *(float2*)(out_ow)           = ow2;
        *(float2*)(out_ow + CH)      = ow2;
        *(float2*)(out_ow + 2u * CH) = ow2;
    }

    float*       out_xw = out_ow + HALF;
    const float* xb     = x + base;

#pragma unroll
    for (unsigned c = 0; c < C; c++) {
        const float* xc = xb + c * CH;
        float v00a = __ldg(xc + o00[0]);
        float v10a = __ldg(xc + o10[0]);
        float v01a = __ldg(xc + o01[0]);
        float v11a = __ldg(xc + o11[0]);
        float v00b = __ldg(xc + o00[1]);
        float v10b = __ldg(xc + o10[1]);
        float v01b = __ldg(xc + o01[1]);
        float v11b = __ldg(xc + o11[1]);

        float sa = m00[0] * v00a + m10[0] * v10a + m01[0] * v01a + m11[0] * v11a;
        float sb = m00[1] * v00b + m10[1] * v10b + m01[1] * v01b + m11[1] * v11b;

        *(float2*)(out_xw + c * CH) = make_float2(sa * wgt[0], sb * wgt[1]);
    }
}

extern "C" void kernel_launch(void* const* d_in, const int* in_sizes, int n_in,
                              void* d_out, int out_size)
{
    const float* x = (const float*)d_in[0];
    const float* f = (const float*)d_in[1];
    float* out = (float*)d_out;

    dim3 block(64, 4, 1);
    dim3 grid(W / 128, H / 4, B * T);   // (10, 180, 10)
    ImageBWarp_65343632441725_kernel<<<grid, block>>>(x, f, out);
}